// round 1
// baseline (speedup 1.0000x reference)
#include <cuda_runtime.h>
#include <math.h>

#define HID 96
#define HC  576
#define NH  6

// ---------------- scratch (device globals; no allocations allowed) ----------------
__device__ float    g_x[20000 * HID];        // node features (current)
__device__ float    g_eemb[200000 * HID];    // edge embeddings
__device__ float    g_xl[20000 * HC];        // x @ Wl + bl
__device__ float    g_xr[20000 * HC];        // x @ Wr + br
__device__ float    g_ee[200000 * HC];       // eemb @ We
__device__ float    g_logits[200000 * NH];   // logits, then exp values (in place)
__device__ unsigned g_umax[20000 * NH];      // segment max (order-preserving uint)
__device__ float    g_den[20000 * NH];       // segment softmax denominator
__device__ float    g_hmean[20000 * HID];    // head-mean aggregation

__device__ __forceinline__ float warpsum32(float v) {
#pragma unroll
    for (int m = 16; m; m >>= 1) v += __shfl_xor_sync(0xffffffffu, v, m);
    return v;
}
__device__ __forceinline__ float gsum16(float v) {
#pragma unroll
    for (int m = 8; m; m >>= 1) v += __shfl_xor_sync(0xffffffffu, v, m);
    return v;
}

// ---------------- encoder: out = relu(LN(in @ W + b)) , Fin in {3,4}, out dim 96 ----
__global__ void encoder_kernel(const float* __restrict__ in, int Fin,
                               const float* __restrict__ W, const float* __restrict__ b,
                               const float* __restrict__ g, const float* __restrict__ beta,
                               float* __restrict__ out, int M)
{
    int w    = (blockIdx.x * blockDim.x + threadIdx.x) >> 5;
    int lane = threadIdx.x & 31;
    if (w >= M) return;
    float xin[4];
#pragma unroll
    for (int k = 0; k < 4; k++) xin[k] = (k < Fin) ? in[(size_t)w * Fin + k] : 0.f;
    float v[3];
#pragma unroll
    for (int j = 0; j < 3; j++) {
        int c = lane + 32 * j;
        float acc = b[c];
        for (int k = 0; k < Fin; k++) acc = fmaf(xin[k], W[k * HID + c], acc);
        v[j] = acc;
    }
    float mu = warpsum32(v[0] + v[1] + v[2]) * (1.f / 96.f);
    float q = 0.f;
#pragma unroll
    for (int j = 0; j < 3; j++) { float d = v[j] - mu; q = fmaf(d, d, q); }
    float rstd = rsqrtf(warpsum32(q) * (1.f / 96.f) + 1e-5f);
#pragma unroll
    for (int j = 0; j < 3; j++) {
        int c = lane + 32 * j;
        float y = (v[j] - mu) * rstd * g[c] + beta[c];
        out[(size_t)w * HID + c] = fmaxf(y, 0.f);
    }
}

// ---------------- GEMM: C[M,576] = A[M,96] @ B[96,576] (+bias) ----------------
#define BM 128
#define BN 64
#define BK 32
#define PAD_AS 132

__global__ __launch_bounds__(256) void gemm96_kernel(
    const float* __restrict__ A, const float* __restrict__ B,
    const float* __restrict__ bias, float* __restrict__ C, int M)
{
    __shared__ float As[BK * PAD_AS];
    __shared__ float Bs[BK * BN];
    int tid = threadIdx.x;
    int m0 = blockIdx.x * BM, n0 = blockIdx.y * BN;
    int tx = tid & 15, ty = tid >> 4;
    float acc[8][4];
#pragma unroll
    for (int i = 0; i < 8; i++)
#pragma unroll
        for (int j = 0; j < 4; j++) acc[i][j] = 0.f;

    for (int k0 = 0; k0 < 96; k0 += BK) {
#pragma unroll
        for (int r = 0; r < 4; r++) {
            int row = (tid >> 3) + r * 32;
            int kq  = (tid & 7) * 4;
            int m   = m0 + row;
            float4 av = make_float4(0.f, 0.f, 0.f, 0.f);
            if (m < M) av = *(const float4*)(A + (size_t)m * 96 + k0 + kq);
            As[(kq + 0) * PAD_AS + row] = av.x;
            As[(kq + 1) * PAD_AS + row] = av.y;
            As[(kq + 2) * PAD_AS + row] = av.z;
            As[(kq + 3) * PAD_AS + row] = av.w;
        }
#pragma unroll
        for (int r = 0; r < 2; r++) {
            int kr = (tid >> 4) + r * 16;
            int nq = (tid & 15) * 4;
            *(float4*)(Bs + kr * BN + nq) =
                *(const float4*)(B + (size_t)(k0 + kr) * HC + n0 + nq);
        }
        __syncthreads();
#pragma unroll
        for (int k = 0; k < BK; k++) {
            float4 a0 = *(float4*)(As + k * PAD_AS + ty * 8);
            float4 a1 = *(float4*)(As + k * PAD_AS + ty * 8 + 4);
            float4 bb = *(float4*)(Bs + k * BN + tx * 4);
            float av[8] = {a0.x, a0.y, a0.z, a0.w, a1.x, a1.y, a1.z, a1.w};
            float bv[4] = {bb.x, bb.y, bb.z, bb.w};
#pragma unroll
            for (int i = 0; i < 8; i++)
#pragma unroll
                for (int j = 0; j < 4; j++)
                    acc[i][j] = fmaf(av[i], bv[j], acc[i][j]);
        }
        __syncthreads();
    }
    float4 bq = make_float4(0.f, 0.f, 0.f, 0.f);
    if (bias) bq = *(const float4*)(bias + n0 + tx * 4);
#pragma unroll
    for (int i = 0; i < 8; i++) {
        int m = m0 + ty * 8 + i;
        if (m < M) {
            float4 o = make_float4(acc[i][0] + bq.x, acc[i][1] + bq.y,
                                   acc[i][2] + bq.z, acc[i][3] + bq.w);
            *(float4*)(C + (size_t)m * HC + n0 + tx * 4) = o;
        }
    }
}

// ---------------- logits + segment max ----------------
__global__ void logits_kernel(const int* __restrict__ src, const int* __restrict__ dst,
                              const float* __restrict__ attw,
                              const float* __restrict__ xl, const float* __restrict__ xr,
                              const float* __restrict__ ee,
                              float* __restrict__ logits, unsigned* __restrict__ umax, int E)
{
    int e    = (blockIdx.x * blockDim.x + threadIdx.x) >> 5;
    int lane = threadIdx.x & 31;
    if (e >= E) return;
    int s = src[e], d = dst[e];
    const float* xls = xl + (size_t)s * HC;
    const float* xrd = xr + (size_t)d * HC;
    const float* eep = ee + (size_t)e * HC;
#pragma unroll
    for (int h = 0; h < NH; h++) {
        float p = 0.f;
#pragma unroll
        for (int j = 0; j < 3; j++) {
            int c = h * 96 + lane + 32 * j;
            float t = xls[c] + xrd[c] + eep[c];
            t = (t > 0.f) ? t : 0.2f * t;
            p = fmaf(t, attw[c], p);
        }
        p = warpsum32(p);
        if (lane == 0) {
            logits[e * NH + h] = p;
            unsigned u = __float_as_uint(p);
            u ^= (u >> 31) ? 0xFFFFFFFFu : 0x80000000u;
            atomicMax(&umax[d * NH + h], u);
        }
    }
}

// ---------------- exp + denominator ----------------
__global__ void expsum_kernel(const int* __restrict__ dst, float* __restrict__ logits,
                              const unsigned* __restrict__ umax, float* __restrict__ den, int E)
{
    int t = blockIdx.x * blockDim.x + threadIdx.x;
    if (t >= E * NH) return;
    int e = t / NH, h = t - e * NH;
    int d = dst[e];
    unsigned u = umax[d * NH + h];
    float m = (u & 0x80000000u) ? __uint_as_float(u ^ 0x80000000u) : __uint_as_float(~u);
    float ex = expf(logits[t] - m);
    logits[t] = ex;
    atomicAdd(&den[d * NH + h], ex);
}

// ---------------- aggregate: hmean[dst] += (1/H) * sum_h alpha_h * xl[src,h,:] -------
__global__ void agg_kernel(const int* __restrict__ src, const int* __restrict__ dst,
                           const float* __restrict__ ex, const float* __restrict__ den,
                           const float* __restrict__ xl, float* __restrict__ hmean, int E)
{
    int e    = (blockIdx.x * blockDim.x + threadIdx.x) >> 5;
    int lane = threadIdx.x & 31;
    if (e >= E) return;
    int s = src[e], d = dst[e];
    float a = 0.f;
    if (lane < NH) a = ex[e * NH + lane] / (den[d * NH + lane] + 1e-16f);
    float alpha[NH];
#pragma unroll
    for (int h = 0; h < NH; h++) alpha[h] = __shfl_sync(0xffffffffu, a, h);
    const float* xls = xl + (size_t)s * HC;
#pragma unroll
    for (int j = 0; j < 3; j++) {
        int c = lane + 32 * j;
        float v = 0.f;
#pragma unroll
        for (int h = 0; h < NH; h++) v = fmaf(alpha[h], xls[h * 96 + c], v);
        atomicAdd(&hmean[(size_t)d * HID + c], v * (1.f / 6.f));
    }
}

// ---------------- node update: x += LN( maybe_elu(hmean + cbias) ) ----------------
__global__ void nodeupd_kernel(const float* __restrict__ cb, const float* __restrict__ g,
                               const float* __restrict__ bt, int doElu,
                               const float* __restrict__ hmean, float* __restrict__ x, int M)
{
    int n    = (blockIdx.x * blockDim.x + threadIdx.x) >> 5;
    int lane = threadIdx.x & 31;
    if (n >= M) return;
    float v[3];
#pragma unroll
    for (int j = 0; j < 3; j++) {
        int c = lane + 32 * j;
        float hv = hmean[(size_t)n * HID + c] + cb[c];
        if (doElu) hv = (hv > 0.f) ? hv : (expf(hv) - 1.f);
        v[j] = hv;
    }
    float mu = warpsum32(v[0] + v[1] + v[2]) * (1.f / 96.f);
    float q = 0.f;
#pragma unroll
    for (int j = 0; j < 3; j++) { float d = v[j] - mu; q = fmaf(d, d, q); }
    float rstd = rsqrtf(warpsum32(q) * (1.f / 96.f) + 1e-5f);
#pragma unroll
    for (int j = 0; j < 3; j++) {
        int c = lane + 32 * j;
        float y = (v[j] - mu) * rstd * g[c] + bt[c];
        x[(size_t)n * HID + c] += y;
    }
}

// ---------------- fused predictor MLP: 288 -> 128(LN,relu) -> 64(LN,relu) -> 1 ------
#define S_P1W 36864
#define S_P2W 8192
#define S_P3W 64
#define S_C1  384
#define S_C2  192
#define S_CTX 9216
#define PRED_SMEM ((S_P1W + S_P2W + S_P3W + S_C1 + S_C2 + S_CTX) * 4)

__global__ __launch_bounds__(256) void predictor_kernel(
    const int* __restrict__ src, const int* __restrict__ dst,
    const float* __restrict__ xnode, const float* __restrict__ eemb,
    const float* __restrict__ p1w, const float* __restrict__ p1b,
    const float* __restrict__ p1g, const float* __restrict__ p1bt,
    const float* __restrict__ p2w, const float* __restrict__ p2b,
    const float* __restrict__ p2g, const float* __restrict__ p2bt,
    const float* __restrict__ p3w, const float* __restrict__ p3b,
    float* __restrict__ out, int E)
{
    extern __shared__ float sm[];
    float* s_p1w = sm;
    float* s_p2w = s_p1w + S_P1W;
    float* s_p3w = s_p2w + S_P2W;
    float* s_c1  = s_p3w + S_P3W;   // p1b | p1g | p1beta (128 each)
    float* s_c2  = s_c1 + S_C1;     // p2b | p2g | p2beta (64 each)
    float* s_ctx = s_c2 + S_C2;     // 32 edges x 288 (reused for h1)

    int tid = threadIdx.x;
    for (int i = tid; i < S_P1W / 4; i += 256) ((float4*)s_p1w)[i] = ((const float4*)p1w)[i];
    for (int i = tid; i < S_P2W / 4; i += 256) ((float4*)s_p2w)[i] = ((const float4*)p2w)[i];
    if (tid < 64) s_p3w[tid] = p3w[tid];
    if (tid < 128) { s_c1[tid] = p1b[tid]; s_c1[128 + tid] = p1g[tid]; s_c1[256 + tid] = p1bt[tid]; }
    if (tid < 64)  { s_c2[tid] = p2b[tid]; s_c2[64 + tid]  = p2g[tid]; s_c2[128 + tid] = p2bt[tid]; }

    int eb = blockIdx.x * 32;
    for (int i = tid; i < 32 * 288; i += 256) {
        int el = i / 288, k = i - el * 288;
        int e = eb + el; if (e > E - 1) e = E - 1;
        float v;
        if (k < 96)       v = xnode[(size_t)src[e] * HID + k];
        else if (k < 192) v = xnode[(size_t)dst[e] * HID + (k - 96)];
        else              v = eemb[(size_t)e * HID + (k - 192)];
        s_ctx[el * 288 + k] = v;
    }
    __syncthreads();

    int p = tid >> 4, jg = tid & 15;
    int el0 = 2 * p, el1 = 2 * p + 1;
    const float* c0 = s_ctx + el0 * 288;
    const float* c1 = s_ctx + el1 * 288;

    // layer 1: outputs jA = jg*4 + i, jB = 64 + jg*4 + i
    float h0a[4] = {0, 0, 0, 0}, h0b[4] = {0, 0, 0, 0};
    float h1a[4] = {0, 0, 0, 0}, h1b[4] = {0, 0, 0, 0};
    int jA = jg * 4, jB = 64 + jg * 4;
    for (int k = 0; k < 288; k++) {
        float a0 = c0[k], a1 = c1[k];
        float4 wA = *(float4*)(s_p1w + k * 128 + jA);
        float4 wB = *(float4*)(s_p1w + k * 128 + jB);
        h0a[0] = fmaf(a0, wA.x, h0a[0]); h0a[1] = fmaf(a0, wA.y, h0a[1]);
        h0a[2] = fmaf(a0, wA.z, h0a[2]); h0a[3] = fmaf(a0, wA.w, h0a[3]);
        h0b[0] = fmaf(a0, wB.x, h0b[0]); h0b[1] = fmaf(a0, wB.y, h0b[1]);
        h0b[2] = fmaf(a0, wB.z, h0b[2]); h0b[3] = fmaf(a0, wB.w, h0b[3]);
        h1a[0] = fmaf(a1, wA.x, h1a[0]); h1a[1] = fmaf(a1, wA.y, h1a[1]);
        h1a[2] = fmaf(a1, wA.z, h1a[2]); h1a[3] = fmaf(a1, wA.w, h1a[3]);
        h1b[0] = fmaf(a1, wB.x, h1b[0]); h1b[1] = fmaf(a1, wB.y, h1b[1]);
        h1b[2] = fmaf(a1, wB.z, h1b[2]); h1b[3] = fmaf(a1, wB.w, h1b[3]);
    }
#pragma unroll
    for (int i = 0; i < 4; i++) {
        h0a[i] += s_c1[jA + i]; h0b[i] += s_c1[jB + i];
        h1a[i] += s_c1[jA + i]; h1b[i] += s_c1[jB + i];
    }
    // LN over 128 per edge (16 lanes x 8 vals)
    {
        float s0 = 0, s1 = 0;
#pragma unroll
        for (int i = 0; i < 4; i++) { s0 += h0a[i] + h0b[i]; s1 += h1a[i] + h1b[i]; }
        float mu0 = gsum16(s0) * (1.f / 128.f), mu1 = gsum16(s1) * (1.f / 128.f);
        float q0 = 0, q1 = 0;
#pragma unroll
        for (int i = 0; i < 4; i++) {
            float d; d = h0a[i] - mu0; q0 = fmaf(d, d, q0); d = h0b[i] - mu0; q0 = fmaf(d, d, q0);
            d = h1a[i] - mu1; q1 = fmaf(d, d, q1); d = h1b[i] - mu1; q1 = fmaf(d, d, q1);
        }
        float r0 = rsqrtf(gsum16(q0) * (1.f / 128.f) + 1e-5f);
        float r1 = rsqrtf(gsum16(q1) * (1.f / 128.f) + 1e-5f);
#pragma unroll
        for (int i = 0; i < 4; i++) {
            h0a[i] = fmaxf((h0a[i] - mu0) * r0 * s_c1[128 + jA + i] + s_c1[256 + jA + i], 0.f);
            h0b[i] = fmaxf((h0b[i] - mu0) * r0 * s_c1[128 + jB + i] + s_c1[256 + jB + i], 0.f);
            h1a[i] = fmaxf((h1a[i] - mu1) * r1 * s_c1[128 + jA + i] + s_c1[256 + jA + i], 0.f);
            h1b[i] = fmaxf((h1b[i] - mu1) * r1 * s_c1[128 + jB + i] + s_c1[256 + jB + i], 0.f);
        }
    }
    __syncthreads();   // everyone done reading ctx
#pragma unroll
    for (int i = 0; i < 4; i++) {
        s_ctx[el0 * 288 + jA + i] = h0a[i]; s_ctx[el0 * 288 + jB + i] = h0b[i];
        s_ctx[el1 * 288 + jA + i] = h1a[i]; s_ctx[el1 * 288 + jB + i] = h1b[i];
    }
    __syncthreads();

    // layer 2: 64 outputs per edge, thread handles j2 = jg*4 + i
    float g0[4] = {0, 0, 0, 0}, g1[4] = {0, 0, 0, 0};
    int j2 = jg * 4;
    const float* hh0 = s_ctx + el0 * 288;
    const float* hh1 = s_ctx + el1 * 288;
    for (int k = 0; k < 128; k++) {
        float a0 = hh0[k], a1 = hh1[k];
        float4 w = *(float4*)(s_p2w + k * 64 + j2);
        g0[0] = fmaf(a0, w.x, g0[0]); g0[1] = fmaf(a0, w.y, g0[1]);
        g0[2] = fmaf(a0, w.z, g0[2]); g0[3] = fmaf(a0, w.w, g0[3]);
        g1[0] = fmaf(a1, w.x, g1[0]); g1[1] = fmaf(a1, w.y, g1[1]);
        g1[2] = fmaf(a1, w.z, g1[2]); g1[3] = fmaf(a1, w.w, g1[3]);
    }
#pragma unroll
    for (int i = 0; i < 4; i++) { g0[i] += s_c2[j2 + i]; g1[i] += s_c2[j2 + i]; }
    {
        float s0 = 0, s1 = 0;
#pragma unroll
        for (int i = 0; i < 4; i++) { s0 += g0[i]; s1 += g1[i]; }
        float mu0 = gsum16(s0) * (1.f / 64.f), mu1 = gsum16(s1) * (1.f / 64.f);
        float q0 = 0, q1 = 0;
#pragma unroll
        for (int i = 0; i < 4; i++) {
            float d; d = g0[i] - mu0; q0 = fmaf(d, d, q0);
            d = g1[i] - mu1; q1 = fmaf(d, d, q1);
        }
        float r0 = rsqrtf(gsum16(q0) * (1.f / 64.f) + 1e-5f);
        float r1 = rsqrtf(gsum16(q1) * (1.f / 64.f) + 1e-5f);
#pragma unroll
        for (int i = 0; i < 4; i++) {
            g0[i] = fmaxf((g0[i] - mu0) * r0 * s_c2[64 + j2 + i] + s_c2[128 + j2 + i], 0.f);
            g1[i] = fmaxf((g1[i] - mu1) * r1 * s_c2[64 + j2 + i] + s_c2[128 + j2 + i], 0.f);
        }
    }
    // layer 3: dot(64)
    float o0 = 0, o1 = 0;
#pragma unroll
    for (int i = 0; i < 4; i++) {
        o0 = fmaf(g0[i], s_p3w[j2 + i], o0);
        o1 = fmaf(g1[i], s_p3w[j2 + i], o1);
    }
    o0 = gsum16(o0); o1 = gsum16(o1);
    if (jg == 0) {
        float pb = p3b[0];
        int e0 = eb + el0, e1 = eb + el1;
        if (e0 < E) out[e0] = o0 + pb;
        if (e1 < E) out[e1] = o1 + pb;
    }
}

// ---------------- launch ----------------
extern "C" void kernel_launch(void* const* d_in, const int* in_sizes, int n_in,
                              void* d_out, int out_size)
{
    const float* x         = (const float*)d_in[0];
    const float* edge_attr = (const float*)d_in[1];
    const int*   edge_idx  = (const int*)d_in[2];
    const float* ne_w = (const float*)d_in[3];
    const float* ne_b = (const float*)d_in[4];
    const float* ne_g = (const float*)d_in[5];
    const float* ne_bt = (const float*)d_in[6];
    const float* ee_w = (const float*)d_in[7];
    const float* ee_b = (const float*)d_in[8];
    const float* ee_g = (const float*)d_in[9];
    const float* ee_bt = (const float*)d_in[10];
    const float* Wl = (const float*)d_in[11];
    const float* bl = (const float*)d_in[12];
    const float* Wr = (const float*)d_in[13];
    const float* br = (const float*)d_in[14];
    const float* We = (const float*)d_in[15];
    const float* attw = (const float*)d_in[16];
    const float* cbias = (const float*)d_in[17];
    const float* lng = (const float*)d_in[18];
    const float* lnb = (const float*)d_in[19];
    const float* p1w = (const float*)d_in[20];
    const float* p1b = (const float*)d_in[21];
    const float* p1g = (const float*)d_in[22];
    const float* p1bt = (const float*)d_in[23];
    const float* p2w = (const float*)d_in[24];
    const float* p2b = (const float*)d_in[25];
    const float* p2g = (const float*)d_in[26];
    const float* p2bt = (const float*)d_in[27];
    const float* p3w = (const float*)d_in[28];
    const float* p3b = (const float*)d_in[29];

    int Nn = in_sizes[0] / 4;
    int E  = in_sizes[1] / 3;
    const int* srcp = edge_idx;
    const int* dstp = edge_idx + E;
    float* outp = (float*)d_out;

    void *px_, *pe_, *pxl_, *pxr_, *pee_, *plog_, *pumax_, *pden_, *phm_;
    cudaGetSymbolAddress(&px_, g_x);
    cudaGetSymbolAddress(&pe_, g_eemb);
    cudaGetSymbolAddress(&pxl_, g_xl);
    cudaGetSymbolAddress(&pxr_, g_xr);
    cudaGetSymbolAddress(&pee_, g_ee);
    cudaGetSymbolAddress(&plog_, g_logits);
    cudaGetSymbolAddress(&pumax_, g_umax);
    cudaGetSymbolAddress(&pden_, g_den);
    cudaGetSymbolAddress(&phm_, g_hmean);
    float* px = (float*)px_;   float* pe = (float*)pe_;
    float* pxl = (float*)pxl_; float* pxr = (float*)pxr_;
    float* pee = (float*)pee_; float* plog = (float*)plog_;
    unsigned* pumax = (unsigned*)pumax_;
    float* pden = (float*)pden_; float* phm = (float*)phm_;

    encoder_kernel<<<(Nn + 7) / 8, 256>>>(x, 4, ne_w, ne_b, ne_g, ne_bt, px, Nn);
    encoder_kernel<<<(E + 7) / 8, 256>>>(edge_attr, 3, ee_w, ee_b, ee_g, ee_bt, pe, E);

    dim3 gN((Nn + BM - 1) / BM, HC / BN);
    dim3 gE((E + BM - 1) / BM, HC / BN);

    for (int l = 0; l < 3; l++) {
        const float* Wl_l = Wl + (size_t)l * 96 * HC;
        const float* Wr_l = Wr + (size_t)l * 96 * HC;
        const float* We_l = We + (size_t)l * 96 * HC;
        gemm96_kernel<<<gN, 256>>>(px, Wl_l, bl + l * HC, pxl, Nn);
        gemm96_kernel<<<gN, 256>>>(px, Wr_l, br + l * HC, pxr, Nn);
        gemm96_kernel<<<gE, 256>>>(pe, We_l, (const float*)0, pee, E);

        cudaMemsetAsync(pumax, 0, (size_t)Nn * NH * sizeof(unsigned), 0);
        cudaMemsetAsync(pden, 0, (size_t)Nn * NH * sizeof(float), 0);
        cudaMemsetAsync(phm, 0, (size_t)Nn * HID * sizeof(float), 0);

        logits_kernel<<<(E + 7) / 8, 256>>>(srcp, dstp, attw + l * NH * 96,
                                            pxl, pxr, pee, plog, pumax, E);
        expsum_kernel<<<(E * NH + 255) / 256, 256>>>(dstp, plog, pumax, pden, E);
        agg_kernel<<<(E + 7) / 8, 256>>>(srcp, dstp, plog, pden, pxl, phm, E);
        nodeupd_kernel<<<(Nn + 7) / 8, 256>>>(cbias + l * HID, lng + l * HID,
                                              lnb + l * HID, (l < 2) ? 1 : 0, phm, px, Nn);
    }

    cudaFuncSetAttribute(predictor_kernel, cudaFuncAttributeMaxDynamicSharedMemorySize,
                         PRED_SMEM);
    predictor_kernel<<<(E + 31) / 32, 256, PRED_SMEM>>>(
        srcp, dstp, px, pe,
        p1w, p1b, p1g, p1bt, p2w, p2b, p2g, p2bt, p3w, p3b, outp, E);
}

// round 2
// speedup vs baseline: 1.1026x; 1.1026x over previous
#include <cuda_runtime.h>
#include <math.h>

#define HID 96
#define HC  576
#define NH  6

typedef unsigned long long ull;

// ---------------- f32x2 packed helpers ----------------
__device__ __forceinline__ ull fma2(ull a, ull b, ull c) {
    ull d;
    asm("fma.rn.f32x2 %0, %1, %2, %3;" : "=l"(d) : "l"(a), "l"(b), "l"(c));
    return d;
}
__device__ __forceinline__ ull pack2(float x, float y) {
    ull r;
    asm("mov.b64 %0, {%1, %2};" : "=l"(r) : "f"(x), "f"(y));
    return r;
}
__device__ __forceinline__ ull dup2(float x) { return pack2(x, x); }
__device__ __forceinline__ float2 unpack2(ull v) {
    float2 r;
    asm("mov.b64 {%0, %1}, %2;" : "=f"(r.x), "=f"(r.y) : "l"(v));
    return r;
}

// ---------------- scratch (device globals; no allocations allowed) ----------------
__device__ float    g_x[20000 * HID];        // node features (current)
__device__ float    g_eemb[200000 * HID];    // edge embeddings
__device__ float    g_xl[20000 * HC];        // x @ Wl + bl
__device__ float    g_xr[20000 * HC];        // x @ Wr + br
__device__ float    g_logits[200000 * NH];   // logits (atomic-accumulated), then exp
__device__ unsigned g_umax[20000 * NH];      // segment max (order-preserving uint)
__device__ float    g_den[20000 * NH];       // segment softmax denominator
__device__ float    g_hmean[20000 * HID];    // head-mean aggregation

__device__ __forceinline__ float warpsum32(float v) {
#pragma unroll
    for (int m = 16; m; m >>= 1) v += __shfl_xor_sync(0xffffffffu, v, m);
    return v;
}
__device__ __forceinline__ float gsum16(float v) {
#pragma unroll
    for (int m = 8; m; m >>= 1) v += __shfl_xor_sync(0xffffffffu, v, m);
    return v;
}

// ---------------- encoder: out = relu(LN(in @ W + b)) ----------------
__global__ void encoder_kernel(const float* __restrict__ in, int Fin,
                               const float* __restrict__ W, const float* __restrict__ b,
                               const float* __restrict__ g, const float* __restrict__ beta,
                               float* __restrict__ out, int M)
{
    int w    = (blockIdx.x * blockDim.x + threadIdx.x) >> 5;
    int lane = threadIdx.x & 31;
    if (w >= M) return;
    float xin[4];
#pragma unroll
    for (int k = 0; k < 4; k++) xin[k] = (k < Fin) ? in[(size_t)w * Fin + k] : 0.f;
    float v[3];
#pragma unroll
    for (int j = 0; j < 3; j++) {
        int c = lane + 32 * j;
        float acc = b[c];
        for (int k = 0; k < Fin; k++) acc = fmaf(xin[k], W[k * HID + c], acc);
        v[j] = acc;
    }
    float mu = warpsum32(v[0] + v[1] + v[2]) * (1.f / 96.f);
    float q = 0.f;
#pragma unroll
    for (int j = 0; j < 3; j++) { float d = v[j] - mu; q = fmaf(d, d, q); }
    float rstd = rsqrtf(warpsum32(q) * (1.f / 96.f) + 1e-5f);
#pragma unroll
    for (int j = 0; j < 3; j++) {
        int c = lane + 32 * j;
        float y = (v[j] - mu) * rstd * g[c] + beta[c];
        out[(size_t)w * HID + c] = fmaxf(y, 0.f);
    }
}

// ---------------- GEMM: C[M,576] = A[M,96] @ B[96,576] ----------------
// FUSED=false: store C (+bias). FUSED=true: no store; fuse GATv2 logit partials:
//   t = acc + xl[src[m],c] + xr[dst[m],c]; leaky_relu; partial = sum_c t*attw[c];
//   segmented half-warp reduce per head; atomicAdd into logits[m*NH+h].
#define BM 128
#define BN 64
#define BK 32
#define PAD_AS 132

template<bool FUSED>
__global__ __launch_bounds__(256) void gemm96_kernel(
    const float* __restrict__ A, const float* __restrict__ B,
    const float* __restrict__ bias, float* __restrict__ C, int M,
    const int* __restrict__ src, const int* __restrict__ dst,
    const float* __restrict__ xl, const float* __restrict__ xr,
    const float* __restrict__ attw, float* __restrict__ logits)
{
    __shared__ float As[BK * PAD_AS];
    __shared__ float Bs[BK * BN];
    int tid = threadIdx.x;
    int m0 = blockIdx.x * BM, n0 = blockIdx.y * BN;
    int tx = tid & 15, ty = tid >> 4;

    ull acc2[4][4];
#pragma unroll
    for (int p = 0; p < 4; p++)
#pragma unroll
        for (int j = 0; j < 4; j++) acc2[p][j] = 0ull;

    for (int k0 = 0; k0 < 96; k0 += BK) {
#pragma unroll
        for (int r = 0; r < 4; r++) {
            int row = (tid >> 3) + r * 32;
            int kq  = (tid & 7) * 4;
            int m   = m0 + row;
            float4 av = make_float4(0.f, 0.f, 0.f, 0.f);
            if (m < M) av = *(const float4*)(A + (size_t)m * 96 + k0 + kq);
            As[(kq + 0) * PAD_AS + row] = av.x;
            As[(kq + 1) * PAD_AS + row] = av.y;
            As[(kq + 2) * PAD_AS + row] = av.z;
            As[(kq + 3) * PAD_AS + row] = av.w;
        }
#pragma unroll
        for (int r = 0; r < 2; r++) {
            int kr = (tid >> 4) + r * 16;
            int nq = (tid & 15) * 4;
            *(float4*)(Bs + kr * BN + nq) =
                *(const float4*)(B + (size_t)(k0 + kr) * HC + n0 + nq);
        }
        __syncthreads();
#pragma unroll
        for (int k = 0; k < BK; k++) {
            float4 a0 = *(float4*)(As + k * PAD_AS + ty * 8);
            float4 a1 = *(float4*)(As + k * PAD_AS + ty * 8 + 4);
            float4 bb = *(float4*)(Bs + k * BN + tx * 4);
            ull ap[4] = {pack2(a0.x, a0.y), pack2(a0.z, a0.w),
                         pack2(a1.x, a1.y), pack2(a1.z, a1.w)};
            ull bd[4] = {dup2(bb.x), dup2(bb.y), dup2(bb.z), dup2(bb.w)};
#pragma unroll
            for (int p = 0; p < 4; p++)
#pragma unroll
                for (int j = 0; j < 4; j++)
                    acc2[p][j] = fma2(ap[p], bd[j], acc2[p][j]);
        }
        __syncthreads();
    }

    // unpack accumulators: accf[i][j] for rows i = 0..7 (m0+ty*8+i)
    float accf[8][4];
#pragma unroll
    for (int p = 0; p < 4; p++)
#pragma unroll
        for (int j = 0; j < 4; j++) {
            float2 u = unpack2(acc2[p][j]);
            accf[2 * p][j]     = u.x;
            accf[2 * p + 1][j] = u.y;
        }

    if (!FUSED) {
        float4 bq = make_float4(0.f, 0.f, 0.f, 0.f);
        if (bias) bq = *(const float4*)(bias + n0 + tx * 4);
#pragma unroll
        for (int i = 0; i < 8; i++) {
            int m = m0 + ty * 8 + i;
            if (m < M) {
                float4 o = make_float4(accf[i][0] + bq.x, accf[i][1] + bq.y,
                                       accf[i][2] + bq.z, accf[i][3] + bq.w);
                *(float4*)(C + (size_t)m * HC + n0 + tx * 4) = o;
            }
        }
    } else {
        int cbase = n0 + tx * 4;
        int h = cbase / 96;            // 4-col group never straddles a head boundary
        float4 awv = *(const float4*)(attw + cbase);
        const unsigned fm = 0xffffffffu;
        int hprev = __shfl_up_sync(fm, h, 1, 16);
        bool leader = (tx == 0) || (hprev != h);
#pragma unroll
        for (int i = 0; i < 8; i++) {
            int m = m0 + ty * 8 + i;
            float partial = 0.f;
            if (m < M) {
                int s = src[m], d = dst[m];
                float4 xlv = *(const float4*)(xl + (size_t)s * HC + cbase);
                float4 xrv = *(const float4*)(xr + (size_t)d * HC + cbase);
                float t0 = accf[i][0] + xlv.x + xrv.x; t0 = (t0 > 0.f) ? t0 : 0.2f * t0;
                float t1 = accf[i][1] + xlv.y + xrv.y; t1 = (t1 > 0.f) ? t1 : 0.2f * t1;
                float t2 = accf[i][2] + xlv.z + xrv.z; t2 = (t2 > 0.f) ? t2 : 0.2f * t2;
                float t3 = accf[i][3] + xlv.w + xrv.w; t3 = (t3 > 0.f) ? t3 : 0.2f * t3;
                partial = t0 * awv.x + t1 * awv.y + t2 * awv.z + t3 * awv.w;
            }
            // segmented reduce over the 16-lane group (contiguous head segments)
#pragma unroll
            for (int off = 1; off < 16; off <<= 1) {
                float ov = __shfl_down_sync(fm, partial, off, 16);
                int   oh = __shfl_down_sync(fm, h, off, 16);
                if (tx + off < 16 && oh == h) partial += ov;
            }
            if (leader && m < M)
                atomicAdd(&logits[(size_t)m * NH + h], partial);
        }
    }
}

// ---------------- segment max over logits ----------------
__global__ void segmax_kernel(const int* __restrict__ dst, const float* __restrict__ logits,
                              unsigned* __restrict__ umax, int E)
{
    int t = blockIdx.x * blockDim.x + threadIdx.x;
    if (t >= E * NH) return;
    int e = t / NH, h = t - e * NH;
    float p = logits[t];
    unsigned u = __float_as_uint(p);
    u ^= (u >> 31) ? 0xFFFFFFFFu : 0x80000000u;
    atomicMax(&umax[dst[e] * NH + h], u);
}

// ---------------- exp + denominator ----------------
__global__ void expsum_kernel(const int* __restrict__ dst, float* __restrict__ logits,
                              const unsigned* __restrict__ umax, float* __restrict__ den, int E)
{
    int t = blockIdx.x * blockDim.x + threadIdx.x;
    if (t >= E * NH) return;
    int e = t / NH, h = t - e * NH;
    int d = dst[e];
    unsigned u = umax[d * NH + h];
    float m = (u & 0x80000000u) ? __uint_as_float(u ^ 0x80000000u) : __uint_as_float(~u);
    float ex = expf(logits[t] - m);
    logits[t] = ex;
    atomicAdd(&den[d * NH + h], ex);
}

// ---------------- aggregate: hmean[dst] += (1/H) * sum_h alpha_h * xl[src,h,:] -------
__global__ void agg_kernel(const int* __restrict__ src, const int* __restrict__ dst,
                           const float* __restrict__ ex, const float* __restrict__ den,
                           const float* __restrict__ xl, float* __restrict__ hmean, int E)
{
    int e    = (blockIdx.x * blockDim.x + threadIdx.x) >> 5;
    int lane = threadIdx.x & 31;
    if (e >= E) return;
    int s = src[e], d = dst[e];
    float a = 0.f;
    if (lane < NH) a = ex[e * NH + lane] / (den[d * NH + lane] + 1e-16f);
    float alpha[NH];
#pragma unroll
    for (int h = 0; h < NH; h++) alpha[h] = __shfl_sync(0xffffffffu, a, h);
    const float* xls = xl + (size_t)s * HC;
#pragma unroll
    for (int j = 0; j < 3; j++) {
        int c = lane + 32 * j;
        float v = 0.f;
#pragma unroll
        for (int h = 0; h < NH; h++) v = fmaf(alpha[h], xls[h * 96 + c], v);
        atomicAdd(&hmean[(size_t)d * HID + c], v * (1.f / 6.f));
    }
}

// ---------------- node update: x += LN( maybe_elu(hmean + cbias) ) ----------------
__global__ void nodeupd_kernel(const float* __restrict__ cb, const float* __restrict__ g,
                               const float* __restrict__ bt, int doElu,
                               const float* __restrict__ hmean, float* __restrict__ x, int M)
{
    int n    = (blockIdx.x * blockDim.x + threadIdx.x) >> 5;
    int lane = threadIdx.x & 31;
    if (n >= M) return;
    float v[3];
#pragma unroll
    for (int j = 0; j < 3; j++) {
        int c = lane + 32 * j;
        float hv = hmean[(size_t)n * HID + c] + cb[c];
        if (doElu) hv = (hv > 0.f) ? hv : (expf(hv) - 1.f);
        v[j] = hv;
    }
    float mu = warpsum32(v[0] + v[1] + v[2]) * (1.f / 96.f);
    float q = 0.f;
#pragma unroll
    for (int j = 0; j < 3; j++) { float d = v[j] - mu; q = fmaf(d, d, q); }
    float rstd = rsqrtf(warpsum32(q) * (1.f / 96.f) + 1e-5f);
#pragma unroll
    for (int j = 0; j < 3; j++) {
        int c = lane + 32 * j;
        float y = (v[j] - mu) * rstd * g[c] + bt[c];
        x[(size_t)n * HID + c] += y;
    }
}

// ---------------- fused predictor MLP: 288 -> 128(LN,relu) -> 64(LN,relu) -> 1 ------
#define S_P1W 36864
#define S_P2W 8192
#define S_P3W 64
#define S_C1  384
#define S_C2  192
#define S_CTX 9216
#define PRED_SMEM ((S_P1W + S_P2W + S_P3W + S_C1 + S_C2 + S_CTX) * 4)

__global__ __launch_bounds__(256) void predictor_kernel(
    const int* __restrict__ src, const int* __restrict__ dst,
    const float* __restrict__ xnode, const float* __restrict__ eemb,
    const float* __restrict__ p1w, const float* __restrict__ p1b,
    const float* __restrict__ p1g, const float* __restrict__ p1bt,
    const float* __restrict__ p2w, const float* __restrict__ p2b,
    const float* __restrict__ p2g, const float* __restrict__ p2bt,
    const float* __restrict__ p3w, const float* __restrict__ p3b,
    float* __restrict__ out, int E)
{
    extern __shared__ float sm[];
    float* s_p1w = sm;
    float* s_p2w = s_p1w + S_P1W;
    float* s_p3w = s_p2w + S_P2W;
    float* s_c1  = s_p3w + S_P3W;
    float* s_c2  = s_c1 + S_C1;
    float* s_ctx = s_c2 + S_C2;

    int tid = threadIdx.x;
    for (int i = tid; i < S_P1W / 4; i += 256) ((float4*)s_p1w)[i] = ((const float4*)p1w)[i];
    for (int i = tid; i < S_P2W / 4; i += 256) ((float4*)s_p2w)[i] = ((const float4*)p2w)[i];
    if (tid < 64) s_p3w[tid] = p3w[tid];
    if (tid < 128) { s_c1[tid] = p1b[tid]; s_c1[128 + tid] = p1g[tid]; s_c1[256 + tid] = p1bt[tid]; }
    if (tid < 64)  { s_c2[tid] = p2b[tid]; s_c2[64 + tid]  = p2g[tid]; s_c2[128 + tid] = p2bt[tid]; }

    int eb = blockIdx.x * 32;
    for (int i = tid; i < 32 * 288; i += 256) {
        int el = i / 288, k = i - el * 288;
        int e = eb + el; if (e > E - 1) e = E - 1;
        float v;
        if (k < 96)       v = xnode[(size_t)src[e] * HID + k];
        else if (k < 192) v = xnode[(size_t)dst[e] * HID + (k - 96)];
        else              v = eemb[(size_t)e * HID + (k - 192)];
        s_ctx[el * 288 + k] = v;
    }
    __syncthreads();

    int p = tid >> 4, jg = tid & 15;
    int el0 = 2 * p, el1 = 2 * p + 1;
    const float* c0 = s_ctx + el0 * 288;
    const float* c1 = s_ctx + el1 * 288;

    // layer 1 (packed f32x2): outputs jA..jA+3, jB..jB+3 for two edges
    int jA = jg * 4, jB = 64 + jg * 4;
    ull H0A0 = 0, H0A1 = 0, H0B0 = 0, H0B1 = 0;
    ull H1A0 = 0, H1A1 = 0, H1B0 = 0, H1B1 = 0;
    for (int k = 0; k < 288; k++) {
        ull a0d = dup2(c0[k]), a1d = dup2(c1[k]);
        float4 wA = *(float4*)(s_p1w + k * 128 + jA);
        float4 wB = *(float4*)(s_p1w + k * 128 + jB);
        ull wa0 = pack2(wA.x, wA.y), wa1 = pack2(wA.z, wA.w);
        ull wb0 = pack2(wB.x, wB.y), wb1 = pack2(wB.z, wB.w);
        H0A0 = fma2(a0d, wa0, H0A0); H0A1 = fma2(a0d, wa1, H0A1);
        H0B0 = fma2(a0d, wb0, H0B0); H0B1 = fma2(a0d, wb1, H0B1);
        H1A0 = fma2(a1d, wa0, H1A0); H1A1 = fma2(a1d, wa1, H1A1);
        H1B0 = fma2(a1d, wb0, H1B0); H1B1 = fma2(a1d, wb1, H1B1);
    }
    float h0a[4], h0b[4], h1a[4], h1b[4];
    { float2 u;
      u = unpack2(H0A0); h0a[0] = u.x; h0a[1] = u.y;
      u = unpack2(H0A1); h0a[2] = u.x; h0a[3] = u.y;
      u = unpack2(H0B0); h0b[0] = u.x; h0b[1] = u.y;
      u = unpack2(H0B1); h0b[2] = u.x; h0b[3] = u.y;
      u = unpack2(H1A0); h1a[0] = u.x; h1a[1] = u.y;
      u = unpack2(H1A1); h1a[2] = u.x; h1a[3] = u.y;
      u = unpack2(H1B0); h1b[0] = u.x; h1b[1] = u.y;
      u = unpack2(H1B1); h1b[2] = u.x; h1b[3] = u.y; }
#pragma unroll
    for (int i = 0; i < 4; i++) {
        h0a[i] += s_c1[jA + i]; h0b[i] += s_c1[jB + i];
        h1a[i] += s_c1[jA + i]; h1b[i] += s_c1[jB + i];
    }
    {
        float s0 = 0, s1 = 0;
#pragma unroll
        for (int i = 0; i < 4; i++) { s0 += h0a[i] + h0b[i]; s1 += h1a[i] + h1b[i]; }
        float mu0 = gsum16(s0) * (1.f / 128.f), mu1 = gsum16(s1) * (1.f / 128.f);
        float q0 = 0, q1 = 0;
#pragma unroll
        for (int i = 0; i < 4; i++) {
            float d; d = h0a[i] - mu0; q0 = fmaf(d, d, q0); d = h0b[i] - mu0; q0 = fmaf(d, d, q0);
            d = h1a[i] - mu1; q1 = fmaf(d, d, q1); d = h1b[i] - mu1; q1 = fmaf(d, d, q1);
        }
        float r0 = rsqrtf(gsum16(q0) * (1.f / 128.f) + 1e-5f);
        float r1 = rsqrtf(gsum16(q1) * (1.f / 128.f) + 1e-5f);
#pragma unroll
        for (int i = 0; i < 4; i++) {
            h0a[i] = fmaxf((h0a[i] - mu0) * r0 * s_c1[128 + jA + i] + s_c1[256 + jA + i], 0.f);
            h0b[i] = fmaxf((h0b[i] - mu0) * r0 * s_c1[128 + jB + i] + s_c1[256 + jB + i], 0.f);
            h1a[i] = fmaxf((h1a[i] - mu1) * r1 * s_c1[128 + jA + i] + s_c1[256 + jA + i], 0.f);
            h1b[i] = fmaxf((h1b[i] - mu1) * r1 * s_c1[128 + jB + i] + s_c1[256 + jB + i], 0.f);
        }
    }
    __syncthreads();
#pragma unroll
    for (int i = 0; i < 4; i++) {
        s_ctx[el0 * 288 + jA + i] = h0a[i]; s_ctx[el0 * 288 + jB + i] = h0b[i];
        s_ctx[el1 * 288 + jA + i] = h1a[i]; s_ctx[el1 * 288 + jB + i] = h1b[i];
    }
    __syncthreads();

    // layer 2 (packed)
    int j2 = jg * 4;
    ull G00 = 0, G01 = 0, G10 = 0, G11 = 0;
    const float* hh0 = s_ctx + el0 * 288;
    const float* hh1 = s_ctx + el1 * 288;
    for (int k = 0; k < 128; k++) {
        ull a0d = dup2(hh0[k]), a1d = dup2(hh1[k]);
        float4 w = *(float4*)(s_p2w + k * 64 + j2);
        ull w0 = pack2(w.x, w.y), w1 = pack2(w.z, w.w);
        G00 = fma2(a0d, w0, G00); G01 = fma2(a0d, w1, G01);
        G10 = fma2(a1d, w0, G10); G11 = fma2(a1d, w1, G11);
    }
    float g0[4], g1[4];
    { float2 u;
      u = unpack2(G00); g0[0] = u.x; g0[1] = u.y;
      u = unpack2(G01); g0[2] = u.x; g0[3] = u.y;
      u = unpack2(G10); g1[0] = u.x; g1[1] = u.y;
      u = unpack2(G11); g1[2] = u.x; g1[3] = u.y; }
#pragma unroll
    for (int i = 0; i < 4; i++) { g0[i] += s_c2[j2 + i]; g1[i] += s_c2[j2 + i]; }
    {
        float s0 = 0, s1 = 0;
#pragma unroll
        for (int i = 0; i < 4; i++) { s0 += g0[i]; s1 += g1[i]; }
        float mu0 = gsum16(s0) * (1.f / 64.f), mu1 = gsum16(s1) * (1.f / 64.f);
        float q0 = 0, q1 = 0;
#pragma unroll
        for (int i = 0; i < 4; i++) {
            float d; d = g0[i] - mu0; q0 = fmaf(d, d, q0);
            d = g1[i] - mu1; q1 = fmaf(d, d, q1);
        }
        float r0 = rsqrtf(gsum16(q0) * (1.f / 64.f) + 1e-5f);
        float r1 = rsqrtf(gsum16(q1) * (1.f / 64.f) + 1e-5f);
#pragma unroll
        for (int i = 0; i < 4; i++) {
            g0[i] = fmaxf((g0[i] - mu0) * r0 * s_c2[64 + j2 + i] + s_c2[128 + j2 + i], 0.f);
            g1[i] = fmaxf((g1[i] - mu1) * r1 * s_c2[64 + j2 + i] + s_c2[128 + j2 + i], 0.f);
        }
    }
    float o0 = 0, o1 = 0;
#pragma unroll
    for (int i = 0; i < 4; i++) {
        o0 = fmaf(g0[i], s_p3w[j2 + i], o0);
        o1 = fmaf(g1[i], s_p3w[j2 + i], o1);
    }
    o0 = gsum16(o0); o1 = gsum16(o1);
    if (jg == 0) {
        float pb = p3b[0];
        int e0 = eb + el0, e1 = eb + el1;
        if (e0 < E) out[e0] = o0 + pb;
        if (e1 < E) out[e1] = o1 + pb;
    }
}

// ---------------- launch ----------------
extern "C" void kernel_launch(void* const* d_in, const int* in_sizes, int n_in,
                              void* d_out, int out_size)
{
    const float* x         = (const float*)d_in[0];
    const float* edge_attr = (const float*)d_in[1];
    const int*   edge_idx  = (const int*)d_in[2];
    const float* ne_w = (const float*)d_in[3];
    const float* ne_b = (const float*)d_in[4];
    const float* ne_g = (const float*)d_in[5];
    const float* ne_bt = (const float*)d_in[6];
    const float* ee_w = (const float*)d_in[7];
    const float* ee_b = (const float*)d_in[8];
    const float* ee_g = (const float*)d_in[9];
    const float* ee_bt = (const float*)d_in[10];
    const float* Wl = (const float*)d_in[11];
    const float* bl = (const float*)d_in[12];
    const float* Wr = (const float*)d_in[13];
    const float* br = (const float*)d_in[14];
    const float* We = (const float*)d_in[15];
    const float* attw = (const float*)d_in[16];
    const float* cbias = (const float*)d_in[17];
    const float* lng = (const float*)d_in[18];
    const float* lnb = (const float*)d_in[19];
    const float* p1w = (const float*)d_in[20];
    const float* p1b = (const float*)d_in[21];
    const float* p1g = (const float*)d_in[22];
    const float* p1bt = (const float*)d_in[23];
    const float* p2w = (const float*)d_in[24];
    const float* p2b = (const float*)d_in[25];
    const float* p2g = (const float*)d_in[26];
    const float* p2bt = (const float*)d_in[27];
    const float* p3w = (const float*)d_in[28];
    const float* p3b = (const float*)d_in[29];

    int Nn = in_sizes[0] / 4;
    int E  = in_sizes[1] / 3;
    const int* srcp = edge_idx;
    const int* dstp = edge_idx + E;
    float* outp = (float*)d_out;

    void *px_, *pe_, *pxl_, *pxr_, *plog_, *pumax_, *pden_, *phm_;
    cudaGetSymbolAddress(&px_, g_x);
    cudaGetSymbolAddress(&pe_, g_eemb);
    cudaGetSymbolAddress(&pxl_, g_xl);
    cudaGetSymbolAddress(&pxr_, g_xr);
    cudaGetSymbolAddress(&plog_, g_logits);
    cudaGetSymbolAddress(&pumax_, g_umax);
    cudaGetSymbolAddress(&pden_, g_den);
    cudaGetSymbolAddress(&phm_, g_hmean);
    float* px = (float*)px_;   float* pe = (float*)pe_;
    float* pxl = (float*)pxl_; float* pxr = (float*)pxr_;
    float* plog = (float*)plog_;
    unsigned* pumax = (unsigned*)pumax_;
    float* pden = (float*)pden_; float* phm = (float*)phm_;

    encoder_kernel<<<(Nn + 7) / 8, 256>>>(x, 4, ne_w, ne_b, ne_g, ne_bt, px, Nn);
    encoder_kernel<<<(E + 7) / 8, 256>>>(edge_attr, 3, ee_w, ee_b, ee_g, ee_bt, pe, E);

    dim3 gN((Nn + BM - 1) / BM, HC / BN);
    dim3 gE((E + BM - 1) / BM, HC / BN);

    for (int l = 0; l < 3; l++) {
        const float* Wl_l = Wl + (size_t)l * 96 * HC;
        const float* Wr_l = Wr + (size_t)l * 96 * HC;
        const float* We_l = We + (size_t)l * 96 * HC;
        gemm96_kernel<false><<<gN, 256>>>(px, Wl_l, bl + l * HC, pxl, Nn,
                                          0, 0, 0, 0, 0, 0);
        gemm96_kernel<false><<<gN, 256>>>(px, Wr_l, br + l * HC, pxr, Nn,
                                          0, 0, 0, 0, 0, 0);

        cudaMemsetAsync(plog, 0, (size_t)E * NH * sizeof(float), 0);
        cudaMemsetAsync(pumax, 0, (size_t)Nn * NH * sizeof(unsigned), 0);
        cudaMemsetAsync(pden, 0, (size_t)Nn * NH * sizeof(float), 0);
        cudaMemsetAsync(phm, 0, (size_t)Nn * HID * sizeof(float), 0);

        // fused edge GEMM + logit partials (ee never materialized)
        gemm96_kernel<true><<<gE, 256>>>(pe, We_l, (const float*)0, (float*)0, E,
                                         srcp, dstp, pxl, pxr,
                                         attw + l * NH * 96, plog);

        segmax_kernel<<<(E * NH + 255) / 256, 256>>>(dstp, plog, pumax, E);
        expsum_kernel<<<(E * NH + 255) / 256, 256>>>(dstp, plog, pumax, pden, E);
        agg_kernel<<<(E + 7) / 8, 256>>>(srcp, dstp, plog, pden, pxl, phm, E);
        nodeupd_kernel<<<(Nn + 7) / 8, 256>>>(cbias + l * HID, lng + l * HID,
                                              lnb + l * HID, (l < 2) ? 1 : 0, phm, px, Nn);
    }

    cudaFuncSetAttribute(predictor_kernel, cudaFuncAttributeMaxDynamicSharedMemorySize,
                         PRED_SMEM);
    predictor_kernel<<<(E + 31) / 32, 256, PRED_SMEM>>>(
        srcp, dstp, px, pe,
        p1w, p1b, p1g, p1bt, p2w, p2b, p2g, p2bt, p3w, p3b, outp, E);
}